// round 6
// baseline (speedup 1.0000x reference)
#include <cuda_runtime.h>
#include <cstdint>
#include <climits>

#define BDIM 512
constexpr int Bn = 16, Nn = 2000, Hh = 512, Ww = 512, MAXD = 10, TOPK_ = 5;
constexpr float CONF = 0.2f, IOUT = 0.4f;
constexpr int KMAX = 256;
constexpr int FILLB = 256;                 // fill blocks
constexpr unsigned FULL = 0xffffffffu;

// Scratch (device globals, allocation-free)
__device__ int g_bi[Bn][MAXD][4];
__device__ int g_k2[Bn][MAXD];

__device__ __forceinline__ float iou_f(float ax1, float ay1, float ax2, float ay2,
                                       float bx1, float by1, float bx2, float by2) {
    float aA = fmaxf(ax2 - ax1, 0.f) * fmaxf(ay2 - ay1, 0.f);
    float aB = fmaxf(bx2 - bx1, 0.f) * fmaxf(by2 - by1, 0.f);
    float ix1 = fmaxf(ax1, bx1), iy1 = fmaxf(ay1, by1);
    float ix2 = fminf(ax2, bx2), iy2 = fminf(ay2, by2);
    float it = fmaxf(ix2 - ix1, 0.f) * fmaxf(iy2 - iy1, 0.f);
    return it / (aA + aB - it + 1e-9f);
}

extern __shared__ unsigned char dynsmem[];
// NMS-block layout:
//   sscore : float[2048]   @ 0       (8192 B)
//   ckey   : ULL[2048]     @ 8192    (16384 B)
//   skeys  : ULL[2048]     @ 24576   (16384 B)
//   skept  : float4[KMAX]  @ 40960   (4096 B)
// total 45056 B

__global__ __launch_bounds__(BDIM) void fused_kernel(const float* __restrict__ region,
                                                     const float* __restrict__ neg,
                                                     float* __restrict__ out,
                                                     float* __restrict__ out_tb,
                                                     float* __restrict__ out_k2) {
    const int t = threadIdx.x;

    // ---------------- fill blocks: stream 1.0f over the whole mask ----------------
    if (blockIdx.x >= Bn) {
        const int fb = blockIdx.x - Bn;
        float4* o4 = (float4*)out;
        const int per = (Bn * Hh * Ww / 4) / FILLB;      // 4096 float4 per block
        float4 one = make_float4(1.f, 1.f, 1.f, 1.f);
        int base = fb * per + t;
#pragma unroll
        for (int i = 0; i < 8; i++) o4[base + i * BDIM] = one;
        return;
    }

    // ---------------- NMS blocks ----------------
    float* sscore = (float*)dynsmem;
    unsigned long long* ckey  = (unsigned long long*)(dynsmem + 8192);
    unsigned long long* skeys = (unsigned long long*)(dynsmem + 24576);
    float4* skept = (float4*)(dynsmem + 40960);

    __shared__ int hist[256];
    __shared__ float sneg[MAXD * 5];
    __shared__ float okx1[MAXD], oky1[MAXD], okx2[MAXD], oky2[MAXD], oksc[MAXD];
    __shared__ float sxb[MAXD][5];
    __shared__ unsigned int sh_maxbits;
    __shared__ int sh_binthr, sh_cnt, sh_found, sh_exh;

    const int b = blockIdx.x;
    const int lane = t & 31;
    const float* rb = region + (size_t)b * Nn * 5;

    if (t < 256) hist[t] = 0;
    if (t == 0) sh_maxbits = 0u;
    __syncthreads();

    // ---- single pass: score stage + max + histogram ----
    unsigned int lm = 0u;
    for (int j = t; j < Nn; j += BDIM) {
        float sc = __ldg(rb + j * 5 + 4);            // scores > 0
        sscore[j] = sc;
        lm = max(lm, __float_as_uint(sc));
        int bin = min(max((int)(sc * 256.0f), 0), 255);
        atomicAdd(&hist[bin], 1);
    }
#pragma unroll
    for (int off = 16; off; off >>= 1)
        lm = max(lm, __shfl_xor_sync(FULL, lm, off));
    if (lane == 0) atomicMax(&sh_maxbits, lm);
    if (t < MAXD * 5) sneg[t] = neg[(size_t)b * MAXD * 5 + t];
    __syncthreads();

    const bool has_conf = __uint_as_float(sh_maxbits) > CONF;
    const float thresh = has_conf ? CONF : 0.0f;
    const int limit = has_conf ? MAXD : TOPK_;

    // ---- candidate selection with escalation fallback ----
    for (int TARGET = 48;; TARGET <<= 2) {
        if (t < 32) {
            int base = 255 - lane * 8;
            int s = 0;
#pragma unroll
            for (int i = 0; i < 8; i++) s += hist[base - i];
            int pre = s;
#pragma unroll
            for (int off = 1; off < 32; off <<= 1) {
                int v = __shfl_up_sync(FULL, pre, off);
                if (lane >= off) pre += v;
            }
            unsigned bal = __ballot_sync(FULL, pre >= TARGET);
            if (bal) {
                int lw = __ffs(bal) - 1;
                if (lane == lw) {
                    int run = pre - s;
                    int binthr = 0;
#pragma unroll
                    for (int i = 0; i < 8; i++) {
                        run += hist[base - i];
                        if (run >= TARGET) { binthr = base - i; break; }
                    }
                    sh_binthr = binthr;
                }
            } else if (lane == 0) {
                sh_binthr = 0;
            }
            if (lane == 0) { sh_exh = (bal == 0); sh_cnt = 0; sh_found = 0; }
        }
        __syncthreads();
        const int binthr = sh_binthr;

        for (int j = t; j < Nn; j += BDIM) {
            float sc = sscore[j];
            if (sc > thresh) {
                int bin = min(max((int)(sc * 256.0f), 0), 255);
                if (bin >= binthr) {
                    int pos = atomicAdd(&sh_cnt, 1);
                    if (pos < 2048)
                        ckey[pos] = ((unsigned long long)__float_as_uint(sc) << 32) |
                                    (unsigned)(Nn - 1 - j);
                }
            }
        }
        __syncthreads();
        const int C = min(sh_cnt, 2048);

        // rank sort (descending; keys unique -> exact stable order)
        for (int i = t; i < C; i += BDIM) {
            unsigned long long ki = ckey[i];
            int r = 0;
            for (int j = 0; j < C; j++) r += (ckey[j] > ki);
            skeys[r] = ki;
        }
        __syncthreads();

        // ---- single-warp greedy NMS: candidate per lane, suppressor-list check ----
        if (t < 32) {
            int nkept = 0, found = 0;
            for (int c0 = 0; c0 < C; c0 += 32) {
                int ci = c0 + lane;
                bool validl = ci < C;
                float x1 = 0.f, y1 = 0.f, x2 = 0.f, y2 = 0.f, sc = 0.f;
                if (validl) {
                    unsigned long long key = skeys[ci];
                    int js = (Nn - 1) - (int)(unsigned)(key & 0xffffffffu);
                    x1 = __ldg(rb + js * 5 + 0);
                    y1 = __ldg(rb + js * 5 + 1);
                    x2 = __ldg(rb + js * 5 + 2);
                    y2 = __ldg(rb + js * 5 + 3);
                    sc = __uint_as_float((unsigned)(key >> 32));
                }
                bool decided = !validl;
                for (int k = 0; k < nkept; k++) {
                    float4 kb = skept[k];
                    if (!decided && iou_f(kb.x, kb.y, kb.z, kb.w, x1, y1, x2, y2) > IOUT)
                        decided = true;
                }
                bool stop = false;
                for (;;) {
                    unsigned und = __ballot_sync(FULL, !decided);
                    if (!und) break;
                    int i0 = __ffs(und) - 1;
                    float ax1 = __shfl_sync(FULL, x1, i0);
                    float ay1 = __shfl_sync(FULL, y1, i0);
                    float ax2 = __shfl_sync(FULL, x2, i0);
                    float ay2 = __shfl_sync(FULL, y2, i0);
                    if (lane == i0) {
                        skept[nkept] = make_float4(x1, y1, x2, y2);
                        decided = true;
                    }
                    nkept++;
                    bool tiny_ok = (ax2 - ax1 >= 1.0f) && (ay2 - ay1 >= 1.0f);
                    if (tiny_ok) {
                        if (lane == i0) {
                            okx1[found] = x1; oky1[found] = y1;
                            okx2[found] = x2; oky2[found] = y2;
                            oksc[found] = sc;
                        }
                        found++;
                        if (found == limit) { stop = true; break; }
                    }
                    if (!decided &&
                        iou_f(ax1, ay1, ax2, ay2, x1, y1, x2, y2) > IOUT)
                        decided = true;
                    if (nkept == KMAX) { stop = true; break; }
                }
                __syncwarp();
                if (stop) break;
            }
            if (lane == 0) sh_found = found;
        }
        __syncthreads();

        if (sh_found >= limit || sh_exh || TARGET >= Nn) break;
    }

    // ---- stage 2: warp-parallel 10-box merge + stable sort + NMS + outputs ----
    if (t < 32) {
        const int cnt = min(sh_found, limit);
        float bx[5];
        bx[0] = bx[1] = bx[2] = bx[3] = 0.f;
        bx[4] = -1.0f;
        if (lane < MAXD) {
            if (lane < cnt) {
                bx[0] = okx1[lane]; bx[1] = oky1[lane];
                bx[2] = okx2[lane]; bx[3] = oky2[lane];
                bx[4] = oksc[lane];
            } else {
#pragma unroll
                for (int c = 0; c < 5; c++) bx[c] = sneg[lane * 5 + c];
            }
        }
        int rank = 0;
#pragma unroll
        for (int j = 0; j < MAXD; j++) {
            float cj = __shfl_sync(FULL, bx[4], j);
            rank += (cj > bx[4]) || (cj == bx[4] && j < lane);
        }
        if (lane < MAXD) {
#pragma unroll
            for (int c = 0; c < 5; c++) sxb[rank][c] = bx[c];
        }
        __syncwarp();
        if (lane < MAXD) {
#pragma unroll
            for (int c = 0; c < 5; c++) bx[c] = sxb[lane][c];
        }
        bool kp = (lane < MAXD) && (bx[4] > 0.0f);
#pragma unroll
        for (int i = 0; i < MAXD; i++) {
            float ax1 = __shfl_sync(FULL, bx[0], i);
            float ay1 = __shfl_sync(FULL, bx[1], i);
            float ax2 = __shfl_sync(FULL, bx[2], i);
            float ay2 = __shfl_sync(FULL, bx[3], i);
            int ki = __shfl_sync(FULL, (int)kp, i);
            if (ki && lane > i && kp) {
                if (iou_f(ax1, ay1, ax2, ay2, bx[0], bx[1], bx[2], bx[3]) > IOUT)
                    kp = false;
            }
        }
        if (lane < MAXD) {
#pragma unroll
            for (int c = 0; c < 4; c++) {
                out_tb[(size_t)b * MAXD * 4 + lane * 4 + c] = kp ? bx[c] : 0.0f;
                g_bi[b][lane][c] = (int)floorf(bx[c] + 0.5f);
            }
            out_k2[(size_t)b * MAXD + lane] = kp ? 1.0f : 0.0f;
            g_k2[b][lane] = kp ? 1 : 0;
        }
    }
}

// zero out covered pixels; one block per (image, slot)
__global__ __launch_bounds__(256) void boxzero_kernel(float* __restrict__ out) {
    int b = blockIdx.x / MAXD, k = blockIdx.x % MAXD;
    if (!g_k2[b][k]) return;
    int x1 = max(g_bi[b][k][0], 0), y1 = max(g_bi[b][k][1], 0);
    int x2 = min(g_bi[b][k][2], Ww), y2 = min(g_bi[b][k][3], Hh);
    int w = x2 - x1, h = y2 - y1;
    if (w <= 0 || h <= 0) return;
    int area = w * h;
    float* base = out + (size_t)b * Hh * Ww;
    for (int i = threadIdx.x; i < area; i += blockDim.x) {
        int y = y1 + i / w, x = x1 + i % w;
        base[y * Ww + x] = 0.0f;
    }
}

extern "C" void kernel_launch(void* const* d_in, const int* in_sizes, int n_in,
                              void* d_out, int out_size) {
    // inputs: [0]=x (unused), [1]=region_boxes (B,N,5), [2]=neg_boxes (B,10,5)
    const float* region = (const float*)d_in[1];
    const float* neg = (const float*)d_in[2];
    float* out = (float*)d_out;
    float* out_tb = out + (size_t)Bn * Hh * Ww;          // target_boxes segment
    float* out_k2 = out_tb + (size_t)Bn * MAXD * 4;      // keep2 segment

    const int smem_bytes = 45056;
    cudaFuncSetAttribute(fused_kernel, cudaFuncAttributeMaxDynamicSharedMemorySize, smem_bytes);

    fused_kernel<<<Bn + FILLB, BDIM, smem_bytes>>>(region, neg, out, out_tb, out_k2);
    boxzero_kernel<<<Bn * MAXD, 256>>>(out);
}